// round 17
// baseline (speedup 1.0000x reference)
#include <cuda_runtime.h>
#include <cstdint>

#define Tlen 1024
#define NCTA 128
#define NTHR 512

typedef unsigned long long ull;

#define TX1 2048   // h1: 128 dims x 4 batches x 4B per dest CTA per step
#define TX2 1024   // h2:  64 dims x 4 batches x 4B per dest CTA per step

struct __align__(16) Smem {
    ull   mb1[8];          // h1 tx-barriers, one per buffer (64 B)
    ull   mb2[8];          // h2 tx-barriers, one per buffer (64 B) -> hc at 128 B
    float hc[8][4][196];   // [buf][batch][h1(0..127) ++ h2(128..191)]
    float xs[1024][4];     // staged x, interleaved [t][b]
};
__shared__ Smem sm;

__device__ __forceinline__ float tanha(float x) {
    float y; asm("tanh.approx.f32 %0, %1;" : "=f"(y) : "f"(x)); return y;
}
__device__ __forceinline__ float sigm(float v) { return fmaf(tanha(0.5f * v), 0.5f, 0.5f); }

__device__ __forceinline__ uint32_t s2u(const void* p) {
    uint32_t a;
    asm("{ .reg .u64 t; cvta.to.shared.u64 t, %1; cvt.u32.u64 %0, t; }" : "=r"(a) : "l"(p));
    return a;
}
__device__ __forceinline__ uint32_t mapa_r(uint32_t saddr, int rank) {
    uint32_t r;
    asm volatile("mapa.shared::cluster.u32 %0, %1, %2;" : "=r"(r) : "r"(saddr), "r"(rank));
    return r;
}
__device__ __forceinline__ void st_async(uint32_t addr, float v, uint32_t mbar) {
    asm volatile(
        "st.async.shared::cluster.mbarrier::complete_tx::bytes.b32 [%0], %1, [%2];"
        :: "r"(addr), "r"(__float_as_uint(v)), "r"(mbar) : "memory");
}
__device__ __forceinline__ void arm_tx(uint32_t mbar, uint32_t bytes) {
    asm volatile("mbarrier.arrive.expect_tx.shared.b64 _, [%0], %1;"
                 :: "r"(mbar), "r"(bytes) : "memory");
}
__device__ __forceinline__ void mwait(uint32_t mbar, uint32_t parity) {
    asm volatile(
        "{\n\t.reg .pred P1;\n\t"
        "WAIT_LOOP_%=:\n\t"
        "mbarrier.try_wait.parity.acquire.cta.shared::cta.b64 P1, [%0], %1, 0x989680;\n\t"
        "@P1 bra.uni WAIT_DONE_%=;\n\t"
        "bra.uni WAIT_LOOP_%=;\n\t"
        "WAIT_DONE_%=:\n\t}"
        :: "r"(mbar), "r"(parity) : "memory");
}
__device__ __forceinline__ void csync() {
    asm volatile("barrier.cluster.arrive.aligned;" ::: "memory");
    asm volatile("barrier.cluster.wait.aligned;" ::: "memory");
}
__device__ __forceinline__ void ffma2(ull& acc, ull a, ull b) {
    asm("fma.rn.f32x2 %0, %1, %2, %0;" : "+l"(acc) : "l"(a), "l"(b));
}
__device__ __forceinline__ float2 u2f2(ull u) {
    float2 f;
    asm("mov.b64 {%0, %1}, %2;" : "=f"(f.x), "=f"(f.y) : "l"(u));
    return f;
}
__device__ __forceinline__ ull pk(float lo, float hi) {
    ull r;
    asm("mov.b64 %0, {%1, %2};" : "=l"(r) : "f"(lo), "f"(hi));
    return r;
}

// 4x4 gate<->batch transpose across lane bits [0:1]; lane G: in s[b]=M[G][b],
// out s[j]=M[j][G].
__device__ __forceinline__ void transpose4(float s[4], int G) {
    const unsigned FULL = 0xffffffffu;
    int g0 = G & 1, g1 = (G >> 1) & 1;
    float x0 = g0 ? s[0] : s[1];
    float x1 = g0 ? s[2] : s[3];
    float y0 = __shfl_xor_sync(FULL, x0, 1);
    float y1 = __shfl_xor_sync(FULL, x1, 1);
    if (g0) { s[0] = y0; s[2] = y1; } else { s[1] = y0; s[3] = y1; }
    x0 = g1 ? s[0] : s[2];
    x1 = g1 ? s[1] : s[3];
    y0 = __shfl_xor_sync(FULL, x0, 2);
    y1 = __shfl_xor_sync(FULL, x1, 2);
    if (g1) { s[0] = y0; s[1] = y1; } else { s[2] = y0; s[3] = y1; }
}

#define HC_BUF_BYTES (4 * 196 * 4)
#define FULL 0xffffffffu

// ---------------- L1 step (macro: BUFR/BUFW/PARR fold to immediates) ----------------
#define L1_STEP(I, BUFR, PARR, BUFW, DOWAIT)                                       \
do {                                                                               \
    float xv_ = sm.xs[(I)][g];                                                     \
    if (DOWAIT) {                                                                  \
        mwait(base0 + MB1O + (BUFR) * 8, (PARR));                                  \
        if (tid == 0) arm_tx(base0 + MB1O + (BUFR) * 8, TX1);                      \
    }                                                                              \
    float s0_[4], s1_[4];                                                          \
    _Pragma("unroll")                                                              \
    for (int b_ = 0; b_ < 4; b_++) {                                               \
        const ulonglong2* hp_ =                                                    \
            reinterpret_cast<const ulonglong2*>(&sm.hc[(BUFR)][b_][0]);            \
        ull a0_ = 0ull, a1_ = 0ull, b0_ = 0ull, b1_ = 0ull;                        \
        _Pragma("unroll")                                                          \
        for (int j_ = 0; j_ < 8; j_++) {                                           \
            ulonglong2 h_ = hp_[kq + 4 * j_];                                      \
            ffma2(a0_, h_.x, w1a[2 * j_]);                                         \
            ffma2(a1_, h_.y, w1a[2 * j_ + 1]);                                     \
            ffma2(b0_, h_.x, w1b[2 * j_]);                                         \
            ffma2(b1_, h_.y, w1b[2 * j_ + 1]);                                     \
        }                                                                          \
        float2 f0_ = u2f2(a0_), f1_ = u2f2(a1_);                                   \
        float2 f2_ = u2f2(b0_), f3_ = u2f2(b1_);                                   \
        s0_[b_] = (f0_.x + f0_.y) + (f1_.x + f1_.y);                               \
        s1_[b_] = (f2_.x + f2_.y) + (f3_.x + f3_.y);                               \
    }                                                                              \
    float sel_[4];                                                                 \
    _Pragma("unroll")                                                              \
    for (int b_ = 0; b_ < 4; b_++) {                                               \
        s0_[b_] += __shfl_xor_sync(FULL, s0_[b_], 4);                              \
        s1_[b_] += __shfl_xor_sync(FULL, s1_[b_], 4);                              \
        float t_ = rsel ? s0_[b_] : s1_[b_];                                       \
        float r_ = __shfl_xor_sync(FULL, t_, 8);                                   \
        sel_[b_] = (rsel ? s1_[b_] : s0_[b_]) + r_;                                \
    }                                                                              \
    transpose4(sel_, g);                                                           \
    float ai_ = fmaf(xv_, wih1s[0], sel_[0] + b1s[0]);                             \
    float af_ = fmaf(xv_, wih1s[1], sel_[1] + b1s[1]);                             \
    float ag_ = fmaf(xv_, wih1s[2], sel_[2] + b1s[2]);                             \
    float ao_ = fmaf(xv_, wih1s[3], sel_[3] + b1s[3]);                             \
    c1 = sigm(af_) * c1 + sigm(ai_) * tanha(ag_);                                  \
    float h_ = sigm(ao_) * tanha(c1);                                              \
    uint32_t off_ = HCO + (BUFW) * HC_BUF_BYTES + l1off;                           \
    st_async(rA + off_, h_, rA + MB1O + (BUFW) * 8);                               \
    st_async(rB + off_, h_, rB + MB1O + (BUFW) * 8);                               \
} while (0)

// ---------------- L2 step ----------------
#define L2_STEP(I, BUFR, PARR, BUFW, DOCOMP, ISLAST)                               \
do {                                                                               \
    float h2v_ = 0.0f;                                                             \
    if (DOCOMP) {                                                                  \
        mwait(base0 + MB2O + (BUFR) * 8, (PARR));                                  \
        if (tid == 256) arm_tx(base0 + MB2O + (BUFR) * 8, TX2);                    \
        const ulonglong2* hp0_ =                                                   \
            reinterpret_cast<const ulonglong2*>(&sm.hc[(BUFR)][0][0]);             \
        ull a0_[4], a1_[4], b0_[4], b1_[4];                                        \
        _Pragma("unroll")                                                          \
        for (int b_ = 0; b_ < 4; b_++) {                                           \
            const ulonglong2* hp_ = hp0_ + b_ * 49;                                \
            a0_[b_] = a1_[b_] = b0_[b_] = b1_[b_] = 0ull;                          \
            _Pragma("unroll")                                                      \
            for (int j_ = 4; j_ < 6; j_++) {                                       \
                ulonglong2 h_ = hp_[ke + 8 * j_];                                  \
                ffma2(a0_[b_], h_.x, w2a[2 * j_]);                                 \
                ffma2(a1_[b_], h_.y, w2a[2 * j_ + 1]);                             \
                ffma2(b0_[b_], h_.x, w2b[2 * j_]);                                 \
                ffma2(b1_[b_], h_.y, w2b[2 * j_ + 1]);                             \
            }                                                                      \
        }                                                                          \
        mwait(base0 + MB1O + (BUFR) * 8, (PARR));                                  \
        float s0_[4], s1_[4];                                                      \
        _Pragma("unroll")                                                          \
        for (int b_ = 0; b_ < 4; b_++) {                                           \
            const ulonglong2* hp_ = hp0_ + b_ * 49;                                \
            _Pragma("unroll")                                                      \
            for (int j_ = 0; j_ < 4; j_++) {                                       \
                ulonglong2 h_ = hp_[ke + 8 * j_];                                  \
                ffma2(a0_[b_], h_.x, w2a[2 * j_]);                                 \
                ffma2(a1_[b_], h_.y, w2a[2 * j_ + 1]);                             \
                ffma2(b0_[b_], h_.x, w2b[2 * j_]);                                 \
                ffma2(b1_[b_], h_.y, w2b[2 * j_ + 1]);                             \
            }                                                                      \
            float2 f0_ = u2f2(a0_[b_]), f1_ = u2f2(a1_[b_]);                       \
            float2 f2_ = u2f2(b0_[b_]), f3_ = u2f2(b1_[b_]);                       \
            s0_[b_] = (f0_.x + f0_.y) + (f1_.x + f1_.y);                           \
            s1_[b_] = (f2_.x + f2_.y) + (f3_.x + f3_.y);                           \
        }                                                                          \
        float sel_[4];                                                             \
        _Pragma("unroll")                                                          \
        for (int b_ = 0; b_ < 4; b_++) {                                           \
            s0_[b_] += __shfl_xor_sync(FULL, s0_[b_], 4);                          \
            s1_[b_] += __shfl_xor_sync(FULL, s1_[b_], 4);                          \
            s0_[b_] += __shfl_xor_sync(FULL, s0_[b_], 8);                          \
            s1_[b_] += __shfl_xor_sync(FULL, s1_[b_], 8);                          \
            float t_ = rsel ? s0_[b_] : s1_[b_];                                   \
            float r_ = __shfl_xor_sync(FULL, t_, 16);                              \
            sel_[b_] = (rsel ? s1_[b_] : s0_[b_]) + r_;                            \
        }                                                                          \
        transpose4(sel_, g);                                                       \
        float ai_ = sel_[0] + b2s[0];                                              \
        float af_ = sel_[1] + b2s[1];                                              \
        float ag_ = sel_[2] + b2s[2];                                              \
        float ao_ = sel_[3] + b2s[3];                                              \
        c2 = sigm(af_) * c2 + sigm(ai_) * tanha(ag_);                              \
        h2v_ = sigm(ao_) * tanha(c2);                                              \
    }                                                                              \
    if ((ISLAST) && (I) == Tlen) {                                                 \
        if ((ke & 3) == 0) out[(4 * cid + g) * 64 + 16 * q + dv2] = h2v_;          \
    } else {                                                                       \
        st_async(rQ + HCO + (BUFW) * HC_BUF_BYTES + l2off, h2v_,                   \
                 rQ + MB2O + (BUFW) * 8);                                          \
    }                                                                              \
} while (0)

__global__ void __launch_bounds__(NTHR, 1) __cluster_dims__(4, 1, 1)
lstm_cluster_kernel(
    const float* __restrict__ x,
    const float* __restrict__ w_ih1,  // [512][1]
    const float* __restrict__ w_hh1,  // [512][128]
    const float* __restrict__ b_ih1,
    const float* __restrict__ b_hh1,
    const float* __restrict__ w_ih2,  // [256][128]
    const float* __restrict__ w_hh2,  // [256][64]
    const float* __restrict__ b_ih2,
    const float* __restrict__ b_hh2,
    float* __restrict__ out)          // [128][64]
{
    const int tid  = threadIdx.x;
    const int lane = tid & 31;
    const int wrp  = tid >> 5;        // 16 warps: 0-7 = L1, 8-15 = L2
    const int q    = blockIdx.x & 3;
    const int cid  = blockIdx.x >> 2;
    const int g    = lane & 3;        // gate (batch after transpose)

    // ---------------- init smem ----------------
    for (int idx = tid; idx < 4 * 1024; idx += NTHR) {
        int b = idx >> 10, t = idx & 1023;
        sm.xs[t][b] = x[(4 * cid + b) * 1024 + t];
    }
    for (int idx = tid; idx < 8 * 4 * 196; idx += NTHR)
        (&sm.hc[0][0][0])[idx] = 0.0f;
    if (tid == 0) {
#pragma unroll
        for (int j = 0; j < 8; j++) {
            uint32_t a1 = s2u(&sm.mb1[j]);
            uint32_t a2 = s2u(&sm.mb2[j]);
            asm volatile("mbarrier.init.shared.b64 [%0], 1;" :: "r"(a1) : "memory");
            asm volatile("mbarrier.init.shared.b64 [%0], 1;" :: "r"(a2) : "memory");
            arm_tx(a1, TX1);
            arm_tx(a2, TX2);
        }
    }

    // ---------------- cluster address constants ----------------
    const uint32_t base0 = s2u(&sm);
    const uint32_t m0    = mapa_r(base0, 0);
    uint32_t dd[4];
    dd[0] = 0;
    dd[1] = mapa_r(base0, 1) - m0;
    dd[2] = mapa_r(base0, 2) - m0;
    dd[3] = mapa_r(base0, 3) - m0;
    const uint32_t HCO  = s2u(&sm.hc[0][0][0]) - base0;
    const uint32_t MB1O = s2u(&sm.mb1[0]) - base0;
    const uint32_t MB2O = s2u(&sm.mb2[0]) - base0;

    csync();  // armed mbars + zeroed smem + xs visible cluster-wide

    if (wrp < 8) {
        // ================= L1 warps: steps 0..1023 =================
        const int kq  = (lane >> 2) & 3;
        const int dlb = (lane >> 4) & 1;
        const int dl  = wrp * 2 + dlb;        // 0..15
        const int rsel = (kq >= 2);
        ull w1a[16], w1b[16];
        {
            const int ra = g * 128 + 32 * q + dl;
            const float* pa = w_hh1 + ra * 128 + kq * 4;
            const float* pb = w_hh1 + (ra + 16) * 128 + kq * 4;
#pragma unroll
            for (int j = 0; j < 8; j++) {
                float4 fa = *reinterpret_cast<const float4*>(pa + j * 16);
                float4 fb = *reinterpret_cast<const float4*>(pb + j * 16);
                w1a[2 * j] = pk(fa.x, fa.y); w1a[2 * j + 1] = pk(fa.z, fa.w);
                w1b[2 * j] = pk(fb.x, fb.y); w1b[2 * j + 1] = pk(fb.z, fb.w);
            }
        }
        float wih1s[4], b1s[4];
#pragma unroll
        for (int j = 0; j < 4; j++) {
            int r = j * 128 + 32 * q + dl + (rsel ? 16 : 0);
            wih1s[j] = w_ih1[r];
            b1s[j]   = b_ih1[r] + b_hh1[r];
        }
        const int dv = dl + (rsel ? 16 : 0);
        const uint32_t l1off = (uint32_t)(g * 196 + 32 * q + dv) * 4;
        const int rep = kq & 1;               // replica -> ranks {2rep, 2rep+1}
        const uint32_t rA = m0 + dd[2 * rep];
        const uint32_t rB = m0 + dd[2 * rep + 1];

        float c1 = 0.0f;
        // prologue: i = 0..7 (buf7 initially zeroed; no ring waits needed)
        L1_STEP(0, 7, 0u, 0, false);
        L1_STEP(1, 0, 0u, 1, true);
        L1_STEP(2, 1, 0u, 2, true);
        L1_STEP(3, 2, 0u, 3, true);
        L1_STEP(4, 3, 0u, 4, true);
        L1_STEP(5, 4, 0u, 5, true);
        L1_STEP(6, 5, 0u, 6, true);
        L1_STEP(7, 6, 0u, 7, true);
        for (int m = 1; m < 128; m++) {
            const int i0 = m << 3;
            const uint32_t pm = (uint32_t)(m & 1), pm1 = pm ^ 1u;
            mwait(base0 + MB2O + 4 * 8, pm1);   // ring: L2 completed step 8m-4
            L1_STEP(i0 + 0, 7, pm1, 0, true);
            L1_STEP(i0 + 1, 0, pm,  1, true);
            L1_STEP(i0 + 2, 1, pm,  2, true);
            L1_STEP(i0 + 3, 2, pm,  3, true);
            mwait(base0 + MB2O + 0, pm);        // ring: L2 completed step 8m
            L1_STEP(i0 + 4, 3, pm, 4, true);
            L1_STEP(i0 + 5, 4, pm, 5, true);
            L1_STEP(i0 + 6, 5, pm, 6, true);
            L1_STEP(i0 + 7, 6, pm, 7, true);
        }
    } else {
        // ================= L2 warps: steps 0..1024 =================
        const int ke  = lane >> 2;            // 0..7
        const int dl2 = wrp - 8;              // 0..7
        const int rsel = (ke >= 4);
        ull w2a[12], w2b[12];
        {
            const int ra = g * 64 + 16 * q + dl2;
            const int rb = ra + 8;
#pragma unroll
            for (int j = 0; j < 6; j++) {
                int k0 = ke * 4 + 32 * j;     // 4-float chunk, never straddles 128
                float4 fa, fb;
                if (k0 < 128) {
                    fa = *reinterpret_cast<const float4*>(w_ih2 + ra * 128 + k0);
                    fb = *reinterpret_cast<const float4*>(w_ih2 + rb * 128 + k0);
                } else {
                    fa = *reinterpret_cast<const float4*>(w_hh2 + ra * 64 + (k0 - 128));
                    fb = *reinterpret_cast<const float4*>(w_hh2 + rb * 64 + (k0 - 128));
                }
                w2a[2 * j] = pk(fa.x, fa.y); w2a[2 * j + 1] = pk(fa.z, fa.w);
                w2b[2 * j] = pk(fb.x, fb.y); w2b[2 * j + 1] = pk(fb.z, fb.w);
            }
        }
        float b2s[4];
#pragma unroll
        for (int j = 0; j < 4; j++) {
            int r = j * 64 + 16 * q + dl2 + (rsel ? 8 : 0);
            b2s[j] = b_ih2[r] + b_hh2[r];
        }
        const int dv2 = dl2 + (rsel ? 8 : 0);
        const uint32_t l2off = (uint32_t)(g * 196 + 128 + 16 * q + dv2) * 4;
        const uint32_t rQ = m0 + dd[ke & 3];  // 1 store/lane covers 4 ranks/row

        float c2 = 0.0f;
        L2_STEP(0, 0, 0u, 0, false, false);   // store h2(0)=0 into buf0
        for (int n = 0; n < 127; n++) {
            const int i0 = (n << 3) + 1;      // i = 8n+1 .. 8n+8
            const uint32_t pn = (uint32_t)(n & 1);
            L2_STEP(i0 + 0, 0, pn, 1, true, false);
            L2_STEP(i0 + 1, 1, pn, 2, true, false);
            L2_STEP(i0 + 2, 2, pn, 3, true, false);
            L2_STEP(i0 + 3, 3, pn, 4, true, false);
            L2_STEP(i0 + 4, 4, pn, 5, true, false);
            L2_STEP(i0 + 5, 5, pn, 6, true, false);
            L2_STEP(i0 + 6, 6, pn, 7, true, false);
            L2_STEP(i0 + 7, 7, pn, 0, true, false);
        }
        // epilogue: i = 1017..1024 (n = 127, parity 1)
        L2_STEP(1017, 0, 1u, 1, true, false);
        L2_STEP(1018, 1, 1u, 2, true, false);
        L2_STEP(1019, 2, 1u, 3, true, false);
        L2_STEP(1020, 3, 1u, 4, true, false);
        L2_STEP(1021, 4, 1u, 5, true, false);
        L2_STEP(1022, 5, 1u, 6, true, false);
        L2_STEP(1023, 6, 1u, 7, true, false);
        L2_STEP(1024, 7, 1u, 0, true, true);  // final hidden -> out
    }

    csync();  // keep smem alive for peers
}

extern "C" void kernel_launch(void* const* d_in, const int* in_sizes, int n_in,
                              void* d_out, int out_size) {
    const float* x     = (const float*)d_in[0];
    const float* w_ih1 = (const float*)d_in[1];
    const float* w_hh1 = (const float*)d_in[2];
    const float* b_ih1 = (const float*)d_in[3];
    const float* b_hh1 = (const float*)d_in[4];
    const float* w_ih2 = (const float*)d_in[5];
    const float* w_hh2 = (const float*)d_in[6];
    const float* b_ih2 = (const float*)d_in[7];
    const float* b_hh2 = (const float*)d_in[8];
    float* out = (float*)d_out;

    lstm_cluster_kernel<<<NCTA, NTHR>>>(
        x, w_ih1, w_hh1, b_ih1, b_hh1, w_ih2, w_hh2, b_ih2, b_hh2, out);
    (void)in_sizes; (void)n_in; (void)out_size;
}